// round 4
// baseline (speedup 1.0000x reference)
#include <cuda_runtime.h>
#include <math.h>

#define D_MODEL 256
#define STATE_N 64
#define SEQ_L   8192
#define HALF_L  4096

// Scratch: K_hat[d, L] complex64 (16 MB) as a device global (no runtime alloc).
__device__ float2 g_Khat[D_MODEL * SEQ_L];

// ---------------------------------------------------------------------------
// packed f32x2 helpers
// ---------------------------------------------------------------------------
typedef unsigned long long u64;

__device__ __forceinline__ u64 pack2(float lo, float hi) {
    u64 r; asm("mov.b64 %0, {%1, %2};" : "=l"(r) : "f"(lo), "f"(hi)); return r;
}
__device__ __forceinline__ void unpack2(u64 v, float& lo, float& hi) {
    asm("mov.b64 {%0, %1}, %2;" : "=f"(lo), "=f"(hi) : "l"(v));
}
__device__ __forceinline__ u64 add2(u64 a, u64 b) {
    u64 r; asm("add.rn.f32x2 %0, %1, %2;" : "=l"(r) : "l"(a), "l"(b)); return r;
}
__device__ __forceinline__ u64 mul2(u64 a, u64 b) {
    u64 r; asm("mul.rn.f32x2 %0, %1, %2;" : "=l"(r) : "l"(a), "l"(b)); return r;
}
__device__ __forceinline__ u64 fma2(u64 a, u64 b, u64 c) {
    u64 r; asm("fma.rn.f32x2 %0, %1, %2, %3;" : "=l"(r) : "l"(a), "l"(b), "l"(c)); return r;
}

// ---------------------------------------------------------------------------
// per-point prologue: z, g, pref  (replicates reference f32 arithmetic)
// ---------------------------------------------------------------------------
__device__ __forceinline__ void point_prologue(int k, float scal,
                                               float& gr, float& gi,
                                               float& pfr, float& pfi)
{
    const float w0 = (float)(-6.283185307179586476925286766559 / (double)SEQ_L);
    float zs, zc;
    sincosf(w0 * (float)k, &zs, &zc);       // z = (zc, zs)

    float dzr = 1.0f + zc;
    float dzi = zs;
    if (k == HALF_L) { dzr = 1.1920929e-7f; dzi = 0.0f; }   // eps clamp
    float idm = 1.0f / (dzr * dzr + dzi * dzi);

    float nr = 1.0f - zc;
    float ni = -zs;
    gr = scal * (nr * dzr + ni * dzi) * idm;
    gi = scal * (ni * dzr - nr * dzi) * idm;
    pfr =  2.0f * dzr * idm;                // pref = 2 / denom_z
    pfi = -2.0f * dzi * idm;
}

// scalar Woodbury tail for one point (sums are conj-accumulated: imag negated here)
__device__ __forceinline__ float2 woodbury(float Ur, float Ui, float Vr, float Vi,
                                           float Qr, float Qi, float Tr, float Ti,
                                           float pfr, float pfi)
{
    Ui = -Ui; Vi = -Vi; Qi = -Qi; Ti = -Ti;
    float PRBr = Ur - Vi, PRBi = Ui + Vr;
    float BRPr = Ur + Vi, BRPi = Ui - Vr;
    float qr = 1.0f + Qr, qi = Qi;
    float iq = 1.0f / (qr * qr + qi * qi);
    float numr = BRPr * PRBr - BRPi * PRBi;
    float numi = BRPr * PRBi + BRPi * PRBr;
    float tr = (numr * qr + numi * qi) * iq;
    float ti = (numi * qr - numr * qi) * iq;
    float hr = Tr - tr;
    float hi = Ti - ti;
    return make_float2(pfr * hr - pfi * hi, pfr * hi + pfi * hr);
}

// ---------------------------------------------------------------------------
// Kernel 1: Cauchy + Woodbury, 2 k-points per thread packed in f32x2 lanes.
// Lane0 = point k, Lane1 = point k + L/2. Weights broadcast to both lanes.
// blockIdx.y = d; 16 blocks x 256 threads cover k = 0..4095.
// ---------------------------------------------------------------------------
__global__ void __launch_bounds__(256) cauchy_kernel(
    const float* __restrict__ Lam_re, const float* __restrict__ Lam_im,
    const float* __restrict__ P_re,   const float* __restrict__ P_im,
    const float* __restrict__ B_re,   const float* __restrict__ B_im,
    const float* __restrict__ log_dt)
{
    __shared__ ulonglong2 s_A[STATE_N];   // (nlam_re2, nlam_im2) broadcast pairs
    __shared__ ulonglong2 s_B[STATE_N];   // (w1r2, w1i2)
    __shared__ ulonglong2 s_C[STATE_N];   // (pp2, bb2)
    __shared__ float      s_scal;

    const int d   = blockIdx.y;
    const int tid = threadIdx.x;

    if (tid < STATE_N) {
        const int idx = d * STATE_N + tid;
        float lr = Lam_re[idx];
        float li = Lam_im[idx];
        float sp = fmaxf(lr, 0.0f) + log1pf(expf(-fabsf(lr)));  // softplus
        float pr = P_re[idx], pi = P_im[idx];
        float br = B_re[idx], bi = B_im[idx];
        float w1r = pr * br + pi * bi;    // conj(P)*B
        float w1i = pr * bi - pi * br;
        float pp  = pr * pr + pi * pi;
        float bb  = br * br + bi * bi;
        // -lam = (+softplus, -Lambda_im)
        s_A[tid] = make_ulonglong2(pack2(sp, sp),   pack2(-li, -li));
        s_B[tid] = make_ulonglong2(pack2(w1r, w1r), pack2(w1i, w1i));
        s_C[tid] = make_ulonglong2(pack2(pp, pp),   pack2(bb, bb));
    }
    if (tid == 0) s_scal = 2.0f * expf(-log_dt[d]);   // 2/dt
    __syncthreads();

    const int k1 = blockIdx.x * blockDim.x + tid;     // 0..4095
    const int k2 = k1 + HALF_L;                       // 4096..8191
    const float scal = s_scal;

    float gr1, gi1, pfr1, pfi1, gr2, gi2, pfr2, pfi2;
    point_prologue(k1, scal, gr1, gi1, pfr1, pfi1);
    point_prologue(k2, scal, gr2, gi2, pfr2, pfi2);

    const u64 grP = pack2(gr1, gr2);
    const u64 giP = pack2(gi1, gi2);

    u64 Ur = 0, Ui = 0, Vr = 0, Vi = 0, Qr = 0, Qi = 0, Tr = 0, Ti = 0;

#pragma unroll 8
    for (int n = 0; n < STATE_N; n++) {
        ulonglong2 A = s_A[n];
        u64 dr2 = add2(grP, A.x);           // g_re - lam_re  (both lanes)
        u64 di2 = add2(giP, A.y);           // g_im - lam_im
        u64 m2  = mul2(dr2, dr2);
        m2      = fma2(di2, di2, m2);       // |d|^2 per lane
        float m_lo, m_hi;
        unpack2(m2, m_lo, m_hi);
        float i_lo, i_hi;
        asm("rcp.approx.f32 %0, %1;" : "=f"(i_lo) : "f"(m_lo));
        asm("rcp.approx.f32 %0, %1;" : "=f"(i_hi) : "f"(m_hi));
        u64 inv2 = pack2(i_lo, i_hi);
        u64 Rr2 = mul2(dr2, inv2);          // conj-R components
        u64 Ri2 = mul2(di2, inv2);
        ulonglong2 B = s_B[n];
        ulonglong2 C = s_C[n];
        Ur = fma2(B.x, Rr2, Ur);  Ui = fma2(B.x, Ri2, Ui);
        Vr = fma2(B.y, Rr2, Vr);  Vi = fma2(B.y, Ri2, Vi);
        Qr = fma2(C.x, Rr2, Qr);  Qi = fma2(C.x, Ri2, Qi);
        Tr = fma2(C.y, Rr2, Tr);  Ti = fma2(C.y, Ri2, Ti);
    }

    float Ur1, Ur2, Ui1, Ui2, Vr1, Vr2, Vi1, Vi2;
    float Qr1, Qr2, Qi1, Qi2, Tr1, Tr2, Ti1, Ti2;
    unpack2(Ur, Ur1, Ur2); unpack2(Ui, Ui1, Ui2);
    unpack2(Vr, Vr1, Vr2); unpack2(Vi, Vi1, Vi2);
    unpack2(Qr, Qr1, Qr2); unpack2(Qi, Qi1, Qi2);
    unpack2(Tr, Tr1, Tr2); unpack2(Ti, Ti1, Ti2);

    g_Khat[d * SEQ_L + k1] = woodbury(Ur1, Ui1, Vr1, Vi1, Qr1, Qi1, Tr1, Ti1, pfr1, pfi1);
    g_Khat[d * SEQ_L + k2] = woodbury(Ur2, Ui2, Vr2, Vi2, Qr2, Qi2, Tr2, Ti2, pfr2, pfi2);
}

// ---------------------------------------------------------------------------
// Kernel 2: Re(ifft_L(X)) = Hermitian fold + 4096-pt radix-4 inverse Stockham.
// One CTA per d-row, 64 KB smem ping-pong.
// ---------------------------------------------------------------------------
__global__ void __launch_bounds__(512) ifft_kernel(float* __restrict__ out)
{
    extern __shared__ float2 sm[];
    float2* x = sm;              // buffer A
    float2* y = sm + HALF_L;     // buffer B

    const int d   = blockIdx.x;
    const int tid = threadIdx.x;
    const int NT  = 512;

    const float2* src = g_Khat + d * SEQ_L;

    // Hermitian fold + even/odd pack:  x[k] = E[k] + i*O[k]
    const float thL = 6.28318530717958647692f / (float)SEQ_L;
    for (int kk = tid; kk < HALF_L; kk += NT) {
        float2 Xa  = src[kk];
        float2 Xam = src[kk == 0 ? 0 : SEQ_L - kk];
        float2 Xb  = src[kk + HALF_L];
        float2 Xbm = src[HALF_L - kk];
        float Ar = 0.5f * (Xa.x + Xam.x), Ai = 0.5f * (Xa.y - Xam.y);
        float Br = 0.5f * (Xb.x + Xbm.x), Bi = 0.5f * (Xb.y - Xbm.y);
        float Er = 0.5f * (Ar + Br), Ei = 0.5f * (Ai + Bi);
        float Dr = 0.5f * (Ar - Br), Di = 0.5f * (Ai - Bi);
        float swr, swi;
        __sincosf(thL * (float)kk, &swi, &swr);
        float Or = Dr * swr - Di * swi;
        float Oi = Dr * swi + Di * swr;
        x[kk] = make_float2(Er - Oi, Ei + Or);
    }
    __syncthreads();

    // 6 radix-4 inverse Stockham stages (4096 = 4^6), e^{+} twiddles
    int n = HALF_L, s = 1, ls = 0;
    while (n > 1) {
        const int m = n >> 2;
        const float th = 6.28318530717958647692f / (float)n;
        for (int u = tid; u < (HALF_L >> 2); u += NT) {
            int p = u >> ls;
            int q = u & (s - 1);
            int base = q + s * p;
            float2 a  = x[base];
            float2 b  = x[base + s * m];
            float2 c  = x[base + s * 2 * m];
            float2 dd = x[base + s * 3 * m];

            float w1i, w1r;
            __sincosf(th * (float)p, &w1i, &w1r);        // w = e^{+i th p}
            float w2r = w1r * w1r - w1i * w1i;           // w^2
            float w2i = 2.0f * w1r * w1i;
            float w3r = w2r * w1r - w2i * w1i;           // w^3
            float w3i = w2r * w1i + w2i * w1r;

            float acr = a.x + c.x, aci = a.y + c.y;      // a+c
            float amr = a.x - c.x, ami = a.y - c.y;      // a-c
            float bdr = b.x + dd.x, bdi = b.y + dd.y;    // b+d
            float bmr = b.x - dd.x, bmi = b.y - dd.y;    // b-d

            // X0 = (a+c)+(b+d); X2 = (a+c)-(b+d)
            float X0r = acr + bdr, X0i = aci + bdi;
            float X2r = acr - bdr, X2i = aci - bdi;
            // X1 = (a-c) + i(b-d); X3 = (a-c) - i(b-d)
            float X1r = amr - bmi, X1i = ami + bmr;
            float X3r = amr + bmi, X3i = ami - bmr;

            int ob = q + s * 4 * p;
            y[ob]         = make_float2(X0r, X0i);
            y[ob + s]     = make_float2(X1r * w1r - X1i * w1i,
                                        X1r * w1i + X1i * w1r);
            y[ob + 2 * s] = make_float2(X2r * w2r - X2i * w2i,
                                        X2r * w2i + X2i * w2r);
            y[ob + 3 * s] = make_float2(X3r * w3r - X3i * w3i,
                                        X3r * w3i + X3i * w3r);
        }
        __syncthreads();
        float2* tmp = x; x = y; y = tmp;
        n = m; s <<= 2; ls += 2;
    }

    // x[m] = K[2m] + i*K[2m+1]  ->  interleaved real output
    const float scale = 1.0f / (float)HALF_L;
    float* dst = out + d * SEQ_L;
    for (int mI = tid; mI < HALF_L; mI += NT) {
        float2 v = x[mI];
        dst[2 * mI]     = v.x * scale;
        dst[2 * mI + 1] = v.y * scale;
    }
}

// ---------------------------------------------------------------------------
extern "C" void kernel_launch(void* const* d_in, const int* in_sizes, int n_in,
                              void* d_out, int out_size)
{
    const float* Lam_re = (const float*)d_in[0];
    const float* Lam_im = (const float*)d_in[1];
    const float* P_re   = (const float*)d_in[2];
    const float* P_im   = (const float*)d_in[3];
    const float* B_re   = (const float*)d_in[4];
    const float* B_im   = (const float*)d_in[5];
    const float* log_dt = (const float*)d_in[6];

    float* out = (float*)d_out;

    // Stage 1: Cauchy + Woodbury -> K_hat (two k-points per thread)
    dim3 gridA(HALF_L / 256, D_MODEL);   // 16 x 256
    cauchy_kernel<<<gridA, 256>>>(Lam_re, Lam_im, P_re, P_im, B_re, B_im, log_dt);

    // Stage 2: Hermitian fold + radix-4 half-length iFFT per row -> K
    cudaFuncSetAttribute(ifft_kernel,
                         cudaFuncAttributeMaxDynamicSharedMemorySize, 65536);
    ifft_kernel<<<D_MODEL, 512, 65536>>>(out);

    // Tail of the output: D buffer (zeros in the reference)
    long kElems = (long)D_MODEL * SEQ_L;
    if ((long)out_size > kElems) {
        cudaMemsetAsync(out + kElems, 0,
                        ((long)out_size - kElems) * sizeof(float), 0);
    }
}